// round 3
// baseline (speedup 1.0000x reference)
#include <cuda_runtime.h>

// Problem dims
#define BATCH 8
#define CIN   256
#define COUT  256
#define IMH   64
#define IMW   64
#define PLANE 4096        // IMH*IMW
#define CK    2304        // CIN*9
#define NOFF  4608        // 2*CK   (w_off elements)
#define NSC   2304        // w_scale elements
#define NDCN  589824      // COUT*CK
#define NTOT  596736      // NOFF+NSC+NDCN
#define CC    8           // channel chunk in main kernel

// ---------- scratch (no allocations allowed -> __device__ globals) ----------
__device__ unsigned int g_absmax[3];
__device__ float g_woffq[NOFF];          // quantized w_off, original layout [2][c][9]
__device__ float g_wscq[NSC];            // quantized w_scale [c][9]
__device__ float g_wt[NDCN];             // quantized w_dcn TRANSPOSED: [(c*9+k)*COUT + o]
__device__ float g_off[BATCH*2*PLANE];   // [b][2][h][w]
__device__ float g_scale[BATCH*PLANE];   // [b][h][w]

// ---------- packed f32x2 FMA (2x fp32 throughput on sm_103a) ----------
__device__ __forceinline__ unsigned long long ffma2(unsigned long long a,
                                                    unsigned long long b,
                                                    unsigned long long c) {
    unsigned long long d;
    asm("fma.rn.f32x2 %0, %1, %2, %3;" : "=l"(d) : "l"(a), "l"(b), "l"(c));
    return d;
}

// ---------- kernel 0: reset absmax slots (graph replays -> must reset) ------
__global__ void k_zero() {
    if (threadIdx.x < 3) g_absmax[threadIdx.x] = 0u;
}

// ---------- kernel 1: per-tensor abs-max (max(|min|,|max|) == max|w|) -------
__global__ void k_absmax(const float* __restrict__ w_off,
                         const float* __restrict__ w_scale,
                         const float* __restrict__ w_dcn) {
    int i = blockIdx.x * blockDim.x + threadIdx.x;
    float v = 0.f;
    int slot = 3;
    if (i < NOFF)                { v = fabsf(w_off[i]);            slot = 0; }
    else if (i < NOFF + NSC)     { v = fabsf(w_scale[i - NOFF]);   slot = 1; }
    else if (i < NTOT)           { v = fabsf(w_dcn[i - NOFF - NSC]); slot = 2; }

    #pragma unroll
    for (int s = 0; s < 3; s++) {
        float m = (slot == s) ? v : 0.f;
        #pragma unroll
        for (int o = 16; o > 0; o >>= 1)
            m = fmaxf(m, __shfl_xor_sync(0xffffffffu, m, o));
        if ((threadIdx.x & 31) == 0 && m > 0.f)
            atomicMax(&g_absmax[s], __float_as_uint(m));  // nonneg floats: uint order == float order
    }
}

// ---------- kernel 2: fake-quantize (match jnp.round = rintf half-to-even) --
__device__ __forceinline__ float fq(float w, float s) {
    float q = rintf(w / s);
    q = fminf(fmaxf(q, -8.f), 7.f);
    return q * s;
}

__global__ void k_quant(const float* __restrict__ w_off,
                        const float* __restrict__ w_scale,
                        const float* __restrict__ w_dcn) {
    int i = blockIdx.x * blockDim.x + threadIdx.x;
    if (i >= NTOT) return;
    if (i < NOFF) {
        float s = fmaxf(__uint_as_float(g_absmax[0]), 1e-8f) / 7.0f;
        g_woffq[i] = fq(w_off[i], s);
    } else if (i < NOFF + NSC) {
        int j = i - NOFF;
        float s = fmaxf(__uint_as_float(g_absmax[1]), 1e-8f) / 7.0f;
        g_wscq[j] = fq(w_scale[j], s);
    } else {
        int j = i - NOFF - NSC;
        float s = fmaxf(__uint_as_float(g_absmax[2]), 1e-8f) / 7.0f;
        int o = j / CK, rem = j - o * CK;        // j = o*2304 + (c*9+k)
        g_wt[rem * COUT + o] = fq(w_dcn[j], s);  // transpose: o contiguous
    }
}

// ---------- kernel 3: offset/scale 3x3 conv (3 outputs over 256 ch) ---------
__global__ void __launch_bounds__(128) k_offscale(const float* __restrict__ x,
                                                  const float* __restrict__ b_off,
                                                  const float* __restrict__ b_scale) {
    __shared__ float sw0[CK], sw1[CK], sws[CK];
    int tid = threadIdx.x;
    for (int i = tid; i < CK; i += 128) {
        sw0[i] = g_woffq[i];
        sw1[i] = g_woffq[CK + i];
        sws[i] = g_wscq[i];
    }
    __syncthreads();

    int b  = blockIdx.y;
    int y  = blockIdx.x * 2 + (tid >> 6);
    int xc = tid & 63;
    float a0 = 0.f, a1 = 0.f, a2 = 0.f;
    const float* xb = x + (size_t)b * CIN * PLANE;

    for (int c = 0; c < CIN; c++) {
        const float* xp = xb + c * PLANE;
        const float* w0 = sw0 + c * 9;
        const float* w1 = sw1 + c * 9;
        const float* ws = sws + c * 9;
        #pragma unroll
        for (int dy = -1; dy <= 1; dy++) {
            int yy = y + dy;
            bool yv = ((unsigned)yy < 64u);
            #pragma unroll
            for (int dx = -1; dx <= 1; dx++) {
                int xx = xc + dx;
                float v = (yv && (unsigned)xx < 64u) ? xp[yy * IMW + xx] : 0.f;
                int t = (dy + 1) * 3 + (dx + 1);
                a0 = fmaf(w0[t], v, a0);
                a1 = fmaf(w1[t], v, a1);
                a2 = fmaf(ws[t], v, a2);
            }
        }
    }
    int p = y * IMW + xc;
    g_off[(b * 2 + 0) * PLANE + p] = a0 + b_off[0];
    g_off[(b * 2 + 1) * PLANE + p] = a1 + b_off[1];
    g_scale[b * PLANE + p] = fmaxf(a2 + b_scale[0], 0.f);
}

// ---------- kernel 4: deform gather + contraction -------------------------
// One block per (b, y)-row: 64 output pixels, 256 threads = one output ch each.
// acc held as 32 packed f32x2 (64 px). Weights pre-transposed -> coalesced.
__global__ void __launch_bounds__(256, 2) k_main(const float* __restrict__ x,
                                                 const float* __restrict__ b_dcn,
                                                 float* __restrict__ out) {
    __shared__ __align__(16) int4   s_idx[9 * IMW];
    __shared__ __align__(16) float4 s_w[9 * IMW];
    __shared__ __align__(16) float  sbuf[CC * 9 * IMW];

    int tid = threadIdx.x;
    int y = blockIdx.x;
    int b = blockIdx.y;

    // --- stage 0: per-(k,px) bilinear records (9*64 = 576) ---
    for (int s = tid; s < 9 * IMW; s += 256) {
        int k  = s >> 6;
        int px = s & 63;
        int p = y * IMW + px;
        float offy = g_off[(b * 2 + 0) * PLANE + p];
        float offx = g_off[(b * 2 + 1) * PLANE + p];
        float sc   = g_scale[b * PLANE + p];
        float ry = (float)(k / 3 - 1);
        float rx = (float)(k % 3 - 1);
        float py  = (float)y  + ry * sc + offy;
        float pxf = (float)px + rx * sc + offx;
        float y0 = floorf(py), x0 = floorf(pxf);
        float fy = py - y0, fx = pxf - x0;
        bool vy0 = (y0 >= 0.f)  && (y0 <= 63.f);
        bool vy1 = (y0 >= -1.f) && (y0 <= 62.f);
        bool vx0 = (x0 >= 0.f)  && (x0 <= 63.f);
        bool vx1 = (x0 >= -1.f) && (x0 <= 62.f);
        int iy0 = (int)fminf(fmaxf(y0,       0.f), 63.f);
        int iy1 = (int)fminf(fmaxf(y0 + 1.f, 0.f), 63.f);
        int ix0 = (int)fminf(fmaxf(x0,       0.f), 63.f);
        int ix1 = (int)fminf(fmaxf(x0 + 1.f, 0.f), 63.f);
        float w00 = (1.f - fy) * (1.f - fx) * ((vy0 && vx0) ? 1.f : 0.f);
        float w01 = (1.f - fy) * fx         * ((vy0 && vx1) ? 1.f : 0.f);
        float w10 = fy * (1.f - fx)         * ((vy1 && vx0) ? 1.f : 0.f);
        float w11 = fy * fx                 * ((vy1 && vx1) ? 1.f : 0.f);
        s_idx[s] = make_int4(iy0 * IMW + ix0, iy0 * IMW + ix1,
                             iy1 * IMW + ix0, iy1 * IMW + ix1);
        s_w[s] = make_float4(w00, w01, w10, w11);
    }
    __syncthreads();

    unsigned long long acc[32];
    #pragma unroll
    for (int j = 0; j < 32; j++) acc[j] = 0ull;

    const float* xb = x + (size_t)b * CIN * PLANE;
    int o = tid;

    for (int cb = 0; cb < CIN; cb += CC) {
        // --- gather CC channels x 9 taps x 64 px into smem ---
        for (int e = tid; e < CC * 9 * IMW; e += 256) {
            int ci = e / (9 * IMW);
            int r  = e - ci * (9 * IMW);
            const float* xp = xb + (cb + ci) * PLANE;
            int4   iv = s_idx[r];
            float4 wv = s_w[r];
            float v = xp[iv.x] * wv.x + xp[iv.y] * wv.y
                    + xp[iv.z] * wv.z + xp[iv.w] * wv.w;
            sbuf[e] = v;
        }
        __syncthreads();

        // --- FMA: acc[px] += W[o, c, k] * sbuf[ci][k][px], packed f32x2 ---
        #pragma unroll 1
        for (int ci = 0; ci < CC; ci++) {
            int c = cb + ci;
            const float* wrow = g_wt + (size_t)c * 9 * COUT + o;
            #pragma unroll 1
            for (int k = 0; k < 9; k++) {
                float wvv = wrow[k * COUT];         // lane=o contiguous -> coalesced
                unsigned long long w2;
                unsigned wu = __float_as_uint(wvv);
                asm("mov.b64 %0, {%1, %2};" : "=l"(w2) : "r"(wu), "r"(wu));
                const ulonglong2* srow =
                    (const ulonglong2*)(sbuf + (ci * 9 + k) * IMW);
                #pragma unroll
                for (int j = 0; j < 16; j++) {
                    ulonglong2 sv = srow[j];        // LDS.128, broadcast across lanes
                    acc[2 * j]     = ffma2(sv.x, w2, acc[2 * j]);
                    acc[2 * j + 1] = ffma2(sv.y, w2, acc[2 * j + 1]);
                }
            }
        }
        __syncthreads();
    }

    float bias = b_dcn[o];
    float* orow = out + (((size_t)b * COUT + o) * IMH + y) * IMW;
    #pragma unroll
    for (int j = 0; j < 32; j++) {
        unsigned lo_u, hi_u;
        asm("mov.b64 {%0, %1}, %2;" : "=r"(lo_u), "=r"(hi_u) : "l"(acc[j]));
        float2 v2 = make_float2(__uint_as_float(lo_u) + bias,
                                __uint_as_float(hi_u) + bias);
        ((float2*)orow)[j] = v2;
    }
}

// ---------- launch ----------------------------------------------------------
extern "C" void kernel_launch(void* const* d_in, const int* in_sizes, int n_in,
                              void* d_out, int out_size) {
    const float* x       = (const float*)d_in[0];
    const float* w_off   = (const float*)d_in[1];
    const float* b_off   = (const float*)d_in[2];
    const float* w_scale = (const float*)d_in[3];
    const float* b_scale = (const float*)d_in[4];
    const float* w_dcn   = (const float*)d_in[5];
    const float* b_dcn   = (const float*)d_in[6];
    float* out = (float*)d_out;

    int nb = (NTOT + 255) / 256;
    k_zero<<<1, 32>>>();
    k_absmax<<<nb, 256>>>(w_off, w_scale, w_dcn);
    k_quant<<<nb, 256>>>(w_off, w_scale, w_dcn);
    k_offscale<<<dim3(IMH / 2, BATCH), 128>>>(x, b_off, b_scale);
    k_main<<<dim3(IMH, BATCH), 256>>>(x, b_dcn, out);
}

// round 6
// speedup vs baseline: 3.2991x; 3.2991x over previous
#include <cuda_runtime.h>
#include <cuda_bf16.h>
#include <cstdint>

// ---------------- problem dims ----------------
#define BATCH 8
#define CIN   256
#define COUT  256
#define IMH   64
#define IMW   64
#define PLANE 4096        // IMH*IMW
#define CK    2304        // CIN*9
#define NOFF  4608        // 2*CK
#define NSC   2304
#define NDCN  589824      // COUT*CK
#define NTOT  596736
#define NCHUNK 72         // 2304 kk / 32 per chunk
#define ABYTES 16384      // per-chunk A: [256 o x 32 k] bf16, swizzled image

// ---------------- smem layout (dynamic) ----------------
#define SO_OY    0        // float[64]
#define SO_OX    256
#define SO_SC    512
#define SO_IDX   768      // int4[576]
#define SO_W     9984     // float4[576]
#define SO_A     19456    // 2 x 16384
#define SO_B     52224    // 2 x (4096 hi + 4096 lo)
#define SMEM_TOTAL 68608

// ---------------- device scratch ----------------
__device__ unsigned int g_absmax[3];
__device__ float g_woffq[NOFF];
__device__ float g_wscq[NSC];
__device__ __align__(128) unsigned char g_wbf[(size_t)NCHUNK * ABYTES]; // swizzled bf16 codes
__device__ float g_part[4 * BATCH * 3 * PLANE]; // offscale partials [q][b][3][plane]

// ---------------- helpers ----------------
__device__ __forceinline__ uint32_t smem_u32(const void* p) {
    uint32_t a;
    asm("{ .reg .u64 t; cvta.to.shared.u64 t, %1; cvt.u32.u64 %0, t; }" : "=r"(a) : "l"(p));
    return a;
}
__device__ __forceinline__ void ldsm4(uint32_t* r, uint32_t addr) {
    asm volatile("ldmatrix.sync.aligned.m8n8.x4.shared.b16 {%0,%1,%2,%3}, [%4];"
                 : "=r"(r[0]), "=r"(r[1]), "=r"(r[2]), "=r"(r[3]) : "r"(addr));
}
__device__ __forceinline__ void mma_bf16(float* d, const uint32_t* a, const uint32_t* b) {
    asm volatile("mma.sync.aligned.m16n8k16.row.col.f32.bf16.bf16.f32 "
                 "{%0,%1,%2,%3}, {%4,%5,%6,%7}, {%8,%9}, {%0,%1,%2,%3};"
                 : "+f"(d[0]), "+f"(d[1]), "+f"(d[2]), "+f"(d[3])
                 : "r"(a[0]), "r"(a[1]), "r"(a[2]), "r"(a[3]), "r"(b[0]), "r"(b[1]));
}
__device__ __forceinline__ void cp16(uint32_t dst, const void* src) {
    asm volatile("cp.async.cg.shared.global [%0], [%1], 16;" :: "r"(dst), "l"(src));
}
#define CP_COMMIT() asm volatile("cp.async.commit_group;")
#define CP_WAIT1()  asm volatile("cp.async.wait_group 1;")

// ---------------- kernel 0: reset absmax ----------------
__global__ void k_zero() {
    if (threadIdx.x < 3) g_absmax[threadIdx.x] = 0u;
}

// ---------------- kernel 1: per-tensor abs-max ----------------
__global__ void k_absmax(const float* __restrict__ w_off,
                         const float* __restrict__ w_scale,
                         const float* __restrict__ w_dcn) {
    int i = blockIdx.x * blockDim.x + threadIdx.x;
    float v = 0.f; int slot = 3;
    if (i < NOFF)            { v = fabsf(w_off[i]);              slot = 0; }
    else if (i < NOFF + NSC) { v = fabsf(w_scale[i - NOFF]);     slot = 1; }
    else if (i < NTOT)       { v = fabsf(w_dcn[i - NOFF - NSC]); slot = 2; }
    #pragma unroll
    for (int s = 0; s < 3; s++) {
        float m = (slot == s) ? v : 0.f;
        #pragma unroll
        for (int o = 16; o > 0; o >>= 1)
            m = fmaxf(m, __shfl_xor_sync(0xffffffffu, m, o));
        if ((threadIdx.x & 31) == 0 && m > 0.f)
            atomicMax(&g_absmax[s], __float_as_uint(m));
    }
}

// ---------------- kernel 2: fake-quant ----------------
__device__ __forceinline__ float fq(float w, float s) {
    float q = rintf(w / s);
    q = fminf(fmaxf(q, -8.f), 7.f);
    return q * s;
}
__global__ void k_quant(const float* __restrict__ w_off,
                        const float* __restrict__ w_scale,
                        const float* __restrict__ w_dcn) {
    int i = blockIdx.x * blockDim.x + threadIdx.x;
    if (i >= NTOT) return;
    if (i < NOFF) {
        float s = fmaxf(__uint_as_float(g_absmax[0]), 1e-8f) / 7.0f;
        g_woffq[i] = fq(w_off[i], s);
    } else if (i < NOFF + NSC) {
        int j = i - NOFF;
        float s = fmaxf(__uint_as_float(g_absmax[1]), 1e-8f) / 7.0f;
        g_wscq[j] = fq(w_scale[j], s);
    } else {
        // w_dcn: INTEGER code (exact in bf16), laid out as the swizzled smem image:
        // chunk ch (32 kk): row o (64B), 16B-chunk c = i>>3, swizzled c ^ ((o>>1)&3)
        int j = i - NOFF - NSC;
        float s = fmaxf(__uint_as_float(g_absmax[2]), 1e-8f) / 7.0f;
        float q = rintf(w_dcn[j] / s);
        q = fminf(fmaxf(q, -8.f), 7.f);
        int o  = j / CK, kk = j - o * CK;
        int ch = kk >> 5, ii = kk & 31;
        unsigned char* base = g_wbf + (size_t)ch * ABYTES;
        int addr = o * 64 + (((ii >> 3) ^ ((o >> 1) & 3)) * 16) + (ii & 7) * 2;
        *(__nv_bfloat16*)(base + addr) = __float2bfloat16(q);
    }
}

// ---------------- kernel 3: offset/scale conv, CIN split 4-way ----------------
__global__ void __launch_bounds__(128) k_offscale(const float* __restrict__ x) {
    __shared__ float sw0[576], sw1[576], sws[576];
    int tid = threadIdx.x;
    int c0 = blockIdx.z * 64;
    for (int i = tid; i < 576; i += 128) {
        sw0[i] = g_woffq[c0 * 9 + i];
        sw1[i] = g_woffq[CK + c0 * 9 + i];
        sws[i] = g_wscq[c0 * 9 + i];
    }
    __syncthreads();

    int b  = blockIdx.y;
    int y  = blockIdx.x * 2 + (tid >> 6);
    int xc = tid & 63;
    float a0 = 0.f, a1 = 0.f, a2 = 0.f;
    const float* xb = x + ((size_t)b * CIN + c0) * PLANE;

    for (int c = 0; c < 64; c++) {
        const float* xp = xb + c * PLANE;
        const float* w0 = sw0 + c * 9;
        const float* w1 = sw1 + c * 9;
        const float* ws = sws + c * 9;
        #pragma unroll
        for (int dy = -1; dy <= 1; dy++) {
            int yy = y + dy;
            bool yv = ((unsigned)yy < 64u);
            #pragma unroll
            for (int dx = -1; dx <= 1; dx++) {
                int xx = xc + dx;
                float v = (yv && (unsigned)xx < 64u) ? xp[yy * IMW + xx] : 0.f;
                int t = (dy + 1) * 3 + (dx + 1);
                a0 = fmaf(w0[t], v, a0);
                a1 = fmaf(w1[t], v, a1);
                a2 = fmaf(ws[t], v, a2);
            }
        }
    }
    int p = y * IMW + xc;
    float* gp = g_part + ((size_t)(blockIdx.z * BATCH + b) * 3) * PLANE;
    gp[p]             = a0;
    gp[PLANE + p]     = a1;
    gp[2 * PLANE + p] = a2;
}

// ---------------- kernel 4: gather + bf16 mma.sync GEMM ----------------
// Block = (b, y): output 256 o x 64 px, K = 2304 fp32 -> hi/lo bf16 split.
// 8 warps: warp w -> o-tile 64 ((w&3)*64), px-tile 32 ((w>>2)*32).
__global__ void __launch_bounds__(256, 1) k_main(const float* __restrict__ x,
                                                 const float* __restrict__ b_off,
                                                 const float* __restrict__ b_scale,
                                                 const float* __restrict__ b_dcn,
                                                 float* __restrict__ out) {
    extern __shared__ __align__(1024) unsigned char sm[];
    uint32_t smb = smem_u32(sm);
    const int tid = threadIdx.x;
    const int wid = tid >> 5, lid = tid & 31;
    const int y = blockIdx.x, b = blockIdx.y;

    // prologue: kick A chunk 0 while stage 0 runs
    {
        const unsigned char* src = g_wbf;
        for (int i = 0; i < 4; i++) {
            int idx = tid + 256 * i;
            cp16(smb + SO_A + idx * 16, src + idx * 16);
        }
        CP_COMMIT();
    }

    // stage 0a: combine offscale partials for this row's 64 px
    float* s_oy = (float*)(sm + SO_OY);
    float* s_ox = (float*)(sm + SO_OX);
    float* s_sc = (float*)(sm + SO_SC);
    if (tid < 64) {
        int p = y * IMW + tid;
        float oy = 0.f, ox = 0.f, sc = 0.f;
        #pragma unroll
        for (int q = 0; q < 4; q++) {
            const float* gp = g_part + ((size_t)(q * BATCH + b) * 3) * PLANE;
            oy += gp[p];
            ox += gp[PLANE + p];
            sc += gp[2 * PLANE + p];
        }
        s_oy[tid] = oy + b_off[0];
        s_ox[tid] = ox + b_off[1];
        s_sc[tid] = fmaxf(sc + b_scale[0], 0.f);
    }
    __syncthreads();

    // stage 0b: bilinear records per (tap, px)
    int4*   s_idx = (int4*)(sm + SO_IDX);
    float4* s_w   = (float4*)(sm + SO_W);
    for (int s = tid; s < 9 * IMW; s += 256) {
        int k  = s >> 6;
        int px = s & 63;
        float sc = s_sc[px];
        float ry = (float)(k / 3 - 1);
        float rx = (float)(k % 3 - 1);
        float py  = (float)y  + ry * sc + s_oy[px];
        float pxf = (float)px + rx * sc + s_ox[px];
        float y0 = floorf(py), x0 = floorf(pxf);
        float fy = py - y0, fx = pxf - x0;
        bool vy0 = (y0 >= 0.f)  && (y0 <= 63.f);
        bool vy1 = (y0 >= -1.f) && (y0 <= 62.f);
        bool vx0 = (x0 >= 0.f)  && (x0 <= 63.f);
        bool vx1 = (x0 >= -1.f) && (x0 <= 62.f);
        int iy0 = (int)fminf(fmaxf(y0,       0.f), 63.f);
        int iy1 = (int)fminf(fmaxf(y0 + 1.f, 0.f), 63.f);
        int ix0 = (int)fminf(fmaxf(x0,       0.f), 63.f);
        int ix1 = (int)fminf(fmaxf(x0 + 1.f, 0.f), 63.f);
        float w00 = (1.f - fy) * (1.f - fx) * ((vy0 && vx0) ? 1.f : 0.f);
        float w01 = (1.f - fy) * fx         * ((vy0 && vx1) ? 1.f : 0.f);
        float w10 = fy * (1.f - fx)         * ((vy1 && vx0) ? 1.f : 0.f);
        float w11 = fy * fx                 * ((vy1 && vx1) ? 1.f : 0.f);
        s_idx[s] = make_int4(iy0 * IMW + ix0, iy0 * IMW + ix1,
                             iy1 * IMW + ix0, iy1 * IMW + ix1);
        s_w[s] = make_float4(w00, w01, w10, w11);
    }
    __syncthreads();

    // per-thread constants
    const float* xb = x + (size_t)b * CIN * PLANE;
    const int px  = tid & 63;        // B-producer px
    const int grp = tid >> 6;        // B-producer kk group (8 consecutive kk)
    const int bst = px * 64 + ((grp ^ ((px >> 1) & 3)) * 16);  // STS offset

    const int o_tile  = (wid & 3) * 64;
    const int px_tile = (wid >> 2) * 32;
    const int arow    = o_tile + (lid & 15);
    const int arow64  = arow * 64;
    const int asw     = ((lid & 15) >> 1) & 3;
    const int ahi     = lid >> 4;
    const int brow    = px_tile + (lid & 7) + ((lid >> 4) & 1) * 8;
    const int brow64  = brow * 64;
    const int bsw     = ((brow & 31) >> 1) & 3;   // px_tile multiple of 32
    const int bsel    = (lid >> 3) & 1;

    float acc[64];
    #pragma unroll
    for (int i = 0; i < 64; i++) acc[i] = 0.f;

    for (int j = 0; j < NCHUNK; j++) {
        // 1. prefetch A chunk j+1
        if (j + 1 < NCHUNK) {
            const unsigned char* src = g_wbf + (size_t)(j + 1) * ABYTES;
            uint32_t dst = smb + SO_A + ((j + 1) & 1) * ABYTES;
            #pragma unroll
            for (int i = 0; i < 4; i++) {
                int idx = tid + 256 * i;
                cp16(dst + idx * 16, src + idx * 16);
            }
        }
        CP_COMMIT();

        // 2. produce B chunk j: gather + hi/lo bf16 split
        {
            int kk0 = j * 32 + grp * 8;
            int c   = kk0 / 9;
            int t9  = kk0 - c * 9;
            float v[8];
            #pragma unroll
            for (int u = 0; u < 8; u++) {
                int r = t9 * 64 + px;
                int4   iv = s_idx[r];
                float4 wv = s_w[r];
                const float* xp = xb + (size_t)c * PLANE;
                v[u] = __ldg(xp + iv.x) * wv.x + __ldg(xp + iv.y) * wv.y
                     + __ldg(xp + iv.z) * wv.z + __ldg(xp + iv.w) * wv.w;
                if (++t9 == 9) { t9 = 0; c++; }
            }
            uint32_t hw[4], lw[4];
            #pragma unroll
            for (int p2 = 0; p2 < 4; p2++) {
                float v0 = v[2 * p2], v1 = v[2 * p2 + 1];
                __nv_bfloat16 h0 = __float2bfloat16(v0);
                __nv_bfloat16 h1 = __float2bfloat16(v1);
                hw[p2] = ((uint32_t)__bfloat16_as_ushort(h1) << 16)
                       |  (uint32_t)__bfloat16_as_ushort(h0);
                __nv_bfloat16 g0 = __float2bfloat16(v0 - __bfloat162float(h0));
                __nv_bfloat16 g1 = __float2bfloat16(v1 - __bfloat162float(h1));
                lw[p2] = ((uint32_t)__bfloat16_as_ushort(g1) << 16)
                       |  (uint32_t)__bfloat16_as_ushort(g0);
            }
            unsigned char* bb = sm + SO_B + (j & 1) * 8192;
            *(uint4*)(bb + bst)        = make_uint4(hw[0], hw[1], hw[2], hw[3]);
            *(uint4*)(bb + 4096 + bst) = make_uint4(lw[0], lw[1], lw[2], lw[3]);
        }

        // 3. wait for A chunk j, publish B chunk j
        CP_WAIT1();
        __syncthreads();

        // 4. MMA over chunk j (K=32: 2 ksteps; A frags reused for hi & lo B)
        {
            uint32_t Ab = smb + SO_A + (j & 1) * ABYTES;
            uint32_t Bb = smb + SO_B + (j & 1) * 8192;
            #pragma unroll
            for (int ks = 0; ks < 2; ks++) {
                uint32_t a[16];
                int ac = ((ks * 2 + ahi) ^ asw) * 16;
                #pragma unroll
                for (int mt = 0; mt < 4; mt++)
                    ldsm4(a + 4 * mt, Ab + arow64 + mt * 1024 + ac);
                int bc = ((ks * 2 + bsel) ^ bsw) * 16;
                #pragma unroll
                for (int h = 0; h < 2; h++) {
                    uint32_t bb[8];
                    uint32_t Bh = Bb + h * 4096 + brow64 + bc;
                    ldsm4(bb,     Bh);
                    ldsm4(bb + 4, Bh + 1024);
                    #pragma unroll
                    for (int mt = 0; mt < 4; mt++)
                        #pragma unroll
                        for (int nt = 0; nt < 4; nt++)
                            mma_bf16(acc + (mt * 4 + nt) * 4, a + 4 * mt,
                                     bb + (nt >> 1) * 4 + (nt & 1) * 2);
                }
            }
        }
        __syncthreads();
    }

    // ---------------- epilogue: scale + bias + store ----------------
    {
        float sdcn = fmaxf(__uint_as_float(g_absmax[2]), 1e-8f) / 7.0f;
        #pragma unroll
        for (int mt = 0; mt < 4; mt++) {
            int o0 = o_tile + mt * 16 + (lid >> 2);
            float bias0 = b_dcn[o0];
            float bias1 = b_dcn[o0 + 8];
            float* r0 = out + (((size_t)b * COUT + o0) * IMH + y) * IMW;
            float* r1 = r0 + 8 * (size_t)PLANE;
            #pragma unroll
            for (int nt = 0; nt < 4; nt++) {
                int pxo = px_tile + nt * 8 + (lid & 3) * 2;
                const float* ac = acc + (mt * 4 + nt) * 4;
                float2 u0 = make_float2(ac[0] * sdcn + bias0, ac[1] * sdcn + bias0);
                float2 u1 = make_float2(ac[2] * sdcn + bias1, ac[3] * sdcn + bias1);
                *(float2*)(r0 + pxo) = u0;
                *(float2*)(r1 + pxo) = u1;
            }
        }
    }
}

// ---------------- launch ----------------
extern "C" void kernel_launch(void* const* d_in, const int* in_sizes, int n_in,
                              void* d_out, int out_size) {
    const float* x       = (const float*)d_in[0];
    const float* w_off   = (const float*)d_in[1];
    const float* b_off   = (const float*)d_in[2];
    const float* w_scale = (const float*)d_in[3];
    const float* b_scale = (const float*)d_in[4];
    const float* w_dcn   = (const float*)d_in[5];
    const float* b_dcn   = (const float*)d_in[6];
    float* out = (float*)d_out;

    static bool attr_done = false;
    if (!attr_done) {
        cudaFuncSetAttribute(k_main, cudaFuncAttributeMaxDynamicSharedMemorySize,
                             SMEM_TOTAL);
        attr_done = true;
    }

    int nb = (NTOT + 255) / 256;
    k_zero<<<1, 32>>>();
    k_absmax<<<nb, 256>>>(w_off, w_scale, w_dcn);
    k_quant<<<nb, 256>>>(w_off, w_scale, w_dcn);
    k_offscale<<<dim3(IMH / 2, BATCH, 4), 128>>>(x);
    k_main<<<dim3(IMH, BATCH), 256, SMEM_TOTAL>>>(x, b_off, b_scale, b_dcn, out);
}